// round 4
// baseline (speedup 1.0000x reference)
#include <cuda_runtime.h>
#include <cuda_bf16.h>

#define NB 16
#define HH 512
#define WW 512
#define PLANE (HH * WW)
#define TOTAL (NB * PLANE)

// Padded layout: stride 516, 516 rows. Data at rows 1..512, cols 2..513.
// Guard cells (row 0, rows 513-515, cols 0-1, cols 514-515) are zero from
// module load and are NEVER written -> stay zero across all replays.
// Gather coords are clamped to [-1, 512]; any clamped/out-of-range corner then
// reads a zero guard cell or carries zero weight, matching zeros-padding
// grid_sample semantics exactly.
#define SP 516
#define PP (SP * SP)          // 266256 elements per padded plane
#define POFF(y, x) (((y) + 1) * SP + ((x) + 2))

__device__ float2 g_dispA[NB * PP];
__device__ float2 g_dispB[NB * PP];
__device__ float  g_ldA[NB * PP];
__device__ float  g_ldB[NB * PP];

__device__ __forceinline__ float2 bilin2(const float2* __restrict__ plane, float sy, float sx) {
    sy = fminf(fmaxf(sy, -1.f), 512.f);
    sx = fminf(fmaxf(sx, -1.f), 512.f);
    float fy0 = floorf(sy), fx0 = floorf(sx);
    float wy = sy - fy0, wx = sx - fx0;
    int y0 = (int)fy0, x0 = (int)fx0;
    int base = POFF(y0, x0);
    float2 v00 = plane[base];
    float2 v01 = plane[base + 1];
    float2 v10 = plane[base + SP];
    float2 v11 = plane[base + SP + 1];
    float w00 = (1.f - wx) * (1.f - wy);
    float w01 = wx * (1.f - wy);
    float w10 = (1.f - wx) * wy;
    float w11 = wx * wy;
    return make_float2(v00.x * w00 + v01.x * w01 + v10.x * w10 + v11.x * w11,
                       v00.y * w00 + v01.y * w01 + v10.y * w10 + v11.y * w11);
}

__device__ __forceinline__ float bilin1(const float* __restrict__ plane, float sy, float sx) {
    sy = fminf(fmaxf(sy, -1.f), 512.f);
    sx = fminf(fmaxf(sx, -1.f), 512.f);
    float fy0 = floorf(sy), fx0 = floorf(sx);
    float wy = sy - fy0, wx = sx - fx0;
    int y0 = (int)fy0, x0 = (int)fx0;
    int base = POFF(y0, x0);
    float v00 = plane[base];
    float v01 = plane[base + 1];
    float v10 = plane[base + SP];
    float v11 = plane[base + SP + 1];
    float w00 = (1.f - wx) * (1.f - wy);
    float w01 = wx * (1.f - wy);
    float w10 = (1.f - wx) * wy;
    float w11 = wx * wy;
    return v00 * w00 + v01 * w01 + v10 * w10 + v11 * w11;
}

// logdet(I + eps*J) 4-term trace series via power-sum recurrence.
__device__ __forceinline__ float logdet_series(float J00, float J01, float J10, float J11) {
    const float eps = 0.0078125f;  // 2^-7
    float t = J00 + J11;
    float d = J00 * J11 - J01 * J10;
    float s2 = t * t - 2.f * d;
    float s3 = t * s2 - d * t;
    float s4 = t * s3 - d * s2;
    const float e2 = eps * eps, e3 = e2 * eps, e4 = e3 * eps;
    return eps * t - 0.5f * e2 * s2 + (e3 * (1.f / 3.f)) * s3 - 0.25f * e4 * s4;
}

// Init (2 pixels/thread): disp0 = eps*vel, ldjac0 from Sobel Jacobian. Writes padded interior.
__global__ void __launch_bounds__(256) init_kernel(const float* __restrict__ vel) {
    int tid = blockIdx.x * blockDim.x + threadIdx.x;
    if (tid >= TOTAL / 2) return;
    int idx = tid << 1;
    int n = idx >> 18;            // / PLANE (2^18)
    int rem = idx & (PLANE - 1);
    int y = rem >> 9;             // / WW
    int x = rem & (WW - 1);       // even

    const float* v0 = vel + (size_t)(2 * n) * PLANE;      // channel 0 (y-vel)
    const float* v1 = v0 + PLANE;                         // channel 1 (x-vel)

    const float eps = 0.0078125f;  // 2^-7

    // replicate padding: clamp rows; columns c0..c3 cover both pixels' stencils
    int ym = max(y - 1, 0), yp = min(y + 1, HH - 1);
    int c0 = max(x - 1, 0), c1 = x, c2 = x + 1, c3 = min(x + 2, WW - 1);
    int rm = ym * WW, rc = y * WW, rp = yp * WW;

    float a0m = v0[rm + c0], a1m = v0[rm + c1], a2m = v0[rm + c2], a3m = v0[rm + c3];
    float a0c = v0[rc + c0], a1c = v0[rc + c1], a2c = v0[rc + c2], a3c = v0[rc + c3];
    float a0p = v0[rp + c0], a1p = v0[rp + c1], a2p = v0[rp + c2], a3p = v0[rp + c3];
    float b0m = v1[rm + c0], b1m = v1[rm + c1], b2m = v1[rm + c2], b3m = v1[rm + c3];
    float b0c = v1[rc + c0], b1c = v1[rc + c1], b2c = v1[rc + c2], b3c = v1[rc + c3];
    float b0p = v1[rp + c0], b1p = v1[rp + c1], b2p = v1[rp + c2], b3p = v1[rp + c3];

    int po = n * PP + POFF(y, x);
    *(float4*)(g_dispA + po) = make_float4(eps * a1c, eps * b1c, eps * a2c, eps * b2c);

    // pixel 0 Jacobian (cols c0,c1,c2)
    float J00a = 0.125f * ((a0p + 2.f * a1p + a2p) - (a0m + 2.f * a1m + a2m));
    float J01a = 0.125f * ((a2m + 2.f * a2c + a2p) - (a0m + 2.f * a0c + a0p));
    float J10a = 0.125f * ((b0p + 2.f * b1p + b2p) - (b0m + 2.f * b1m + b2m));
    float J11a = 0.125f * ((b2m + 2.f * b2c + b2p) - (b0m + 2.f * b0c + b0p));
    // pixel 1 Jacobian (cols c1,c2,c3)
    float J00b = 0.125f * ((a1p + 2.f * a2p + a3p) - (a1m + 2.f * a2m + a3m));
    float J01b = 0.125f * ((a3m + 2.f * a3c + a3p) - (a1m + 2.f * a1c + a1p));
    float J10b = 0.125f * ((b1p + 2.f * b2p + b3p) - (b1m + 2.f * b2m + b3m));
    float J11b = 0.125f * ((b3m + 2.f * b3c + b3p) - (b1m + 2.f * b1c + b1p));

    *(float2*)(g_ldA + po) = make_float2(logdet_series(J00a, J01a, J10a, J11a),
                                         logdet_series(J00b, J01b, J10b, J11b));
}

// One squaring step, fused, 2 pixels/thread:
//   disp_new = disp_old + warp(disp_old, disp_old)
//   ldjac_new = ldjac_old + warp(ldjac_old, disp_new)
template <bool SRC_A, bool FINAL>
__global__ void __launch_bounds__(256) step_kernel(float* __restrict__ out_disp,
                                                   float* __restrict__ out_ld) {
    int tid = blockIdx.x * blockDim.x + threadIdx.x;
    if (tid >= TOTAL / 2) return;
    int idx = tid << 1;
    int n = idx >> 18;
    int rem = idx & (PLANE - 1);
    int y = rem >> 9;
    int x = rem & (WW - 1);   // even

    const float2* __restrict__ dp = (SRC_A ? g_dispA : g_dispB) + (size_t)n * PP;
    const float*  __restrict__ lp = (SRC_A ? g_ldA   : g_ldB)   + (size_t)n * PP;

    const float SC = (float)HH / (float)(HH - 1);

    int po = POFF(y, x);
    float4 dc = *(const float4*)(dp + po);   // pixel0=(dc.x,dc.y), pixel1=(dc.z,dc.w)
    float2 lc = *(const float2*)(lp + po);

    float fy = (float)y, fx = (float)x;
    float sy0 = (fy + dc.x) * SC - 0.5f;
    float sx0 = (fx + dc.y) * SC - 0.5f;
    float sy1 = (fy + dc.z) * SC - 0.5f;
    float sx1 = (fx + 1.f + dc.w) * SC - 0.5f;

    float2 s0 = bilin2(dp, sy0, sx0);
    float2 s1 = bilin2(dp, sy1, sx1);

    float dn0x = dc.x + s0.x, dn0y = dc.y + s0.y;
    float dn1x = dc.z + s1.x, dn1y = dc.w + s1.y;

    float l0 = lc.x + bilin1(lp, (fy + dn0x) * SC - 0.5f, (fx + dn0y) * SC - 0.5f);
    float l1 = lc.y + bilin1(lp, (fy + dn1x) * SC - 0.5f, (fx + 1.f + dn1y) * SC - 0.5f);

    if (FINAL) {
        // planar output: disp [N,2,H,W] then ldjac [N,1,H,W]
        *(float2*)(out_disp + (size_t)(2 * n) * PLANE + rem)     = make_float2(dn0x, dn1x);
        *(float2*)(out_disp + (size_t)(2 * n + 1) * PLANE + rem) = make_float2(dn0y, dn1y);
        *(float2*)(out_ld + (size_t)n * PLANE + rem)             = make_float2(l0, l1);
    } else {
        float2* __restrict__ ddst = (SRC_A ? g_dispB : g_dispA) + (size_t)n * PP;
        float*  __restrict__ ldst = (SRC_A ? g_ldB   : g_ldA)   + (size_t)n * PP;
        *(float4*)(ddst + po) = make_float4(dn0x, dn0y, dn1x, dn1y);
        *(float2*)(ldst + po) = make_float2(l0, l1);
    }
}

extern "C" void kernel_launch(void* const* d_in, const int* in_sizes, int n_in,
                              void* d_out, int out_size) {
    const float* vel = (const float*)d_in[0];
    float* out = (float*)d_out;
    float* out_disp = out;
    float* out_ld = out + (size_t)NB * 2 * PLANE;

    const int threads = 256;
    const int blocks = (TOTAL / 2 + threads - 1) / threads;

    init_kernel<<<blocks, threads>>>(vel);
    // 7 steps: A->B, B->A, A->B, B->A, A->B, B->A, A->out
    step_kernel<true,  false><<<blocks, threads>>>(out_disp, out_ld);
    step_kernel<false, false><<<blocks, threads>>>(out_disp, out_ld);
    step_kernel<true,  false><<<blocks, threads>>>(out_disp, out_ld);
    step_kernel<false, false><<<blocks, threads>>>(out_disp, out_ld);
    step_kernel<true,  false><<<blocks, threads>>>(out_disp, out_ld);
    step_kernel<false, false><<<blocks, threads>>>(out_disp, out_ld);
    step_kernel<true,  true ><<<blocks, threads>>>(out_disp, out_ld);
}